// round 2
// baseline (speedup 1.0000x reference)
#include <cuda_runtime.h>
#include <math.h>

#define Bb 128
#define Cc 512
#define Pp 196
#define Tt 32
#define Vv 10403
#define Ee 128
#define Uu 256
#define Gg 1024      // 4*U
#define Kcat 896     // C + E + U

// ---------------- scratch (device globals; no allocation allowed) -------------
__device__ float g_mean[Bb*Cc];          // [B,C]
__device__ float g_keys[Bb*Uu*Pp];       // [B,U,P]
__device__ float g_xemb[Bb*Tt*Ee];       // [B,T,E]
__device__ float g_h[Bb*Uu];
__device__ float g_c[Bb*Uu];
__device__ float g_q[Bb*Uu];
__device__ float g_gates[Bb*Gg];
__device__ float g_attn[Bb*Tt*Cc];       // [B,T,C]
__device__ float g_hall[Bb*Tt*Uu];       // [B,T,U]

// ---------------- mean over spatial positions ---------------------------------
__global__ void mean_kernel(const float* __restrict__ img) {
    int row  = blockIdx.x * 8 + (threadIdx.x >> 5);   // b*C + c
    int lane = threadIdx.x & 31;
    const float* src = img + (size_t)row * Pp;
    float s = 0.f;
    for (int p = lane; p < Pp; p += 32) s += src[p];
    #pragma unroll
    for (int o = 16; o > 0; o >>= 1) s += __shfl_down_sync(0xffffffffu, s, o);
    if (lane == 0) g_mean[row] = s * (1.0f / 196.0f);
}

// ---------------- h0 / c0 init -------------------------------------------------
__global__ void hc0_kernel(const float* __restrict__ Wh0, const float* __restrict__ bh0,
                           const float* __restrict__ Wc0, const float* __restrict__ bc0) {
    __shared__ float mf[Cc];
    int b = blockIdx.x, tid = threadIdx.x;
    mf[tid]       = g_mean[b*Cc + tid];
    mf[tid + 256] = g_mean[b*Cc + 256 + tid];
    __syncthreads();
    int u = tid;
    const float* wh = Wh0 + (size_t)u * Cc;
    const float* wc = Wc0 + (size_t)u * Cc;
    float ah = 0.f, ac = 0.f;
    #pragma unroll 4
    for (int c = 0; c < Cc; c++) { ah += mf[c]*wh[c]; ac += mf[c]*wc[c]; }
    float h0 = ah + bh0[u];
    float c0 = ac + bc0[u];
    g_h[b*Uu + u] = h0;
    g_c[b*Uu + u] = c0;
    g_q[b*Uu + u] = c0;   // reference: first query is the initial cell
}

// ---------------- embedding gather --------------------------------------------
__global__ void emb_kernel(const int* __restrict__ ix, const float* __restrict__ emb) {
    int idx = blockIdx.x * 256 + threadIdx.x;   // < B*T*E
    int r = idx >> 7, e = idx & 127;
    g_xemb[idx] = emb[(size_t)ix[r] * Ee + e];
}

// ---------------- keys[b] = W_key @ img[b]  (NN gemm, batched) -----------------
__global__ void keys_kernel(const float* __restrict__ Wk, const float* __restrict__ bk,
                            const float* __restrict__ img) {
    int b  = blockIdx.z;
    int n0 = blockIdx.x * 64;   // p
    int m0 = blockIdx.y * 64;   // u
    __shared__ __align__(16) float sA[16][68];  // [k][m]
    __shared__ __align__(16) float sB[16][68];  // [k][n]
    int tid = threadIdx.x;
    int tx = tid & 15, ty = tid >> 4;
    float acc[4][4] = {};
    const float* imgb = img + (size_t)b * Cc * Pp;
    for (int k0 = 0; k0 < Cc; k0 += 16) {
        #pragma unroll
        for (int i = 0; i < 4; i++) {
            int id = tid + i*256;
            int mm = id >> 4, k = id & 15;
            sA[k][mm] = Wk[(size_t)(m0+mm)*Cc + k0 + k];
        }
        #pragma unroll
        for (int i = 0; i < 4; i++) {
            int id = tid + i*256;
            int k = id >> 6, nn = id & 63;
            int p = n0 + nn;
            sB[k][nn] = (p < Pp) ? imgb[(size_t)(k0+k)*Pp + p] : 0.f;
        }
        __syncthreads();
        #pragma unroll
        for (int kk = 0; kk < 16; kk++) {
            float4 a4 = *(const float4*)&sA[kk][ty*4];
            float4 b4 = *(const float4*)&sB[kk][tx*4];
            acc[0][0] += a4.x*b4.x; acc[0][1] += a4.x*b4.y; acc[0][2] += a4.x*b4.z; acc[0][3] += a4.x*b4.w;
            acc[1][0] += a4.y*b4.x; acc[1][1] += a4.y*b4.y; acc[1][2] += a4.y*b4.z; acc[1][3] += a4.y*b4.w;
            acc[2][0] += a4.z*b4.x; acc[2][1] += a4.z*b4.y; acc[2][2] += a4.z*b4.z; acc[2][3] += a4.z*b4.w;
            acc[3][0] += a4.w*b4.x; acc[3][1] += a4.w*b4.y; acc[3][2] += a4.w*b4.z; acc[3][3] += a4.w*b4.w;
        }
        __syncthreads();
    }
    #pragma unroll
    for (int i = 0; i < 4; i++) {
        int u = m0 + ty*4 + i;
        float bias = bk[u];
        #pragma unroll
        for (int j = 0; j < 4; j++) {
            int p = n0 + tx*4 + j;
            if (p < Pp) g_keys[((size_t)b*Uu + u)*Pp + p] = acc[i][j] + bias;
        }
    }
}

// ---------------- per-step attention: scores, softmax, maps, attn --------------
__global__ void attn_kernel(int t, const float* __restrict__ img, float* __restrict__ maps) {
    int b = blockIdx.x, tid = threadIdx.x;
    __shared__ float qs[Uu];
    __shared__ float sc[256];
    __shared__ float ws[256];
    qs[tid] = g_q[b*Uu + tid];
    __syncthreads();
    float s = -INFINITY;
    if (tid < Pp) {
        float acc = 0.f;
        const float* kb = g_keys + (size_t)b*Uu*Pp + tid;
        #pragma unroll 8
        for (int u = 0; u < Uu; u++) acc += qs[u] * kb[(size_t)u*Pp];
        s = acc * 0.0625f;   // 1/sqrt(256)
    }
    sc[tid] = s;
    __syncthreads();
    for (int o = 128; o > 0; o >>= 1) {
        if (tid < o) sc[tid] = fmaxf(sc[tid], sc[tid+o]);
        __syncthreads();
    }
    float mx = sc[0];
    __syncthreads();
    float ex = (tid < Pp) ? expf(s - mx) : 0.f;
    sc[tid] = ex;
    __syncthreads();
    for (int o = 128; o > 0; o >>= 1) {
        if (tid < o) sc[tid] += sc[tid+o];
        __syncthreads();
    }
    float inv = 1.f / sc[0];
    float w = ex * inv;
    ws[tid] = w;
    if (tid < Pp) maps[((size_t)b*Tt + t)*Pp + tid] = w;
    __syncthreads();
    int wid = tid >> 5, lane = tid & 31;
    for (int c = wid; c < Cc; c += 8) {
        const float* row = img + ((size_t)b*Cc + c)*Pp;
        float a = 0.f;
        for (int p = lane; p < Pp; p += 32) a += ws[p]*row[p];
        #pragma unroll
        for (int o = 16; o > 0; o >>= 1) a += __shfl_down_sync(0xffffffffu, a, o);
        if (lane == 0) g_attn[((size_t)b*Tt + t)*Cc + c] = a;
    }
}

// ---------------- per-step gates GEMM: [128 x 1024], K=896 ---------------------
// A row b = [emb_t(128) | attn(512) | h(256)], B = [W_ih | W_hh] row j (k-contig)
__global__ void gates_kernel(int t, const float* __restrict__ Wih, const float* __restrict__ bih,
                             const float* __restrict__ Whh, const float* __restrict__ bhh) {
    int n0 = blockIdx.x * 64;   // j
    int m0 = blockIdx.y * 16;   // b
    __shared__ float sA[32][17];   // [k][m]
    __shared__ float sB[64][33];   // [n][k]
    int tid = threadIdx.x;
    int n  = tid & 63;
    int mB = (tid >> 6) * 4;
    float acc[4] = {0.f, 0.f, 0.f, 0.f};
    for (int k0 = 0; k0 < Kcat; k0 += 32) {
        #pragma unroll
        for (int i = 0; i < 2; i++) {
            int id = tid + i*256;
            int mm = id >> 5, k = id & 31;
            int gk = k0 + k, bb = m0 + mm;
            float v;
            if (gk < Ee)            v = g_xemb[(bb*Tt + t)*Ee + gk];
            else if (gk < Ee + Cc)  v = g_attn[((size_t)bb*Tt + t)*Cc + (gk - Ee)];
            else                    v = g_h[bb*Uu + (gk - Ee - Cc)];
            sA[k][mm] = v;
        }
        #pragma unroll
        for (int i = 0; i < 8; i++) {
            int id = tid + i*256;
            int nn = id >> 5, k = id & 31;
            int gk = k0 + k, j = n0 + nn;
            sB[nn][k] = (gk < Ee + Cc) ? Wih[(size_t)j*(Ee+Cc) + gk]
                                       : Whh[(size_t)j*Uu + (gk - Ee - Cc)];
        }
        __syncthreads();
        #pragma unroll
        for (int kk = 0; kk < 32; kk++) {
            float bv = sB[n][kk];
            acc[0] += sA[kk][mB+0] * bv;
            acc[1] += sA[kk][mB+1] * bv;
            acc[2] += sA[kk][mB+2] * bv;
            acc[3] += sA[kk][mB+3] * bv;
        }
        __syncthreads();
    }
    int j = n0 + n;
    float bias = bih[j] + bhh[j];
    #pragma unroll
    for (int i = 0; i < 4; i++)
        g_gates[(m0 + mB + i)*Gg + j] = acc[i] + bias;
}

// ---------------- per-step LSTM elementwise update ------------------------------
__global__ void lstm_kernel(int t) {
    int b = blockIdx.x, u = threadIdx.x;
    const float* g = g_gates + b*Gg;
    float ig = g[u], fg = g[u+256], gg = g[u+512], og = g[u+768];
    float si = 1.f / (1.f + expf(-ig));
    float sf = 1.f / (1.f + expf(-fg));
    float so = 1.f / (1.f + expf(-og));
    float cn = sf * g_c[b*Uu + u] + si * tanhf(gg);
    float hn = so * tanhf(cn);
    g_c[b*Uu + u] = cn;
    g_h[b*Uu + u] = hn;
    g_q[b*Uu + u] = hn;
    g_hall[(b*Tt + t)*Uu + u] = hn;
}

// ---------------- final logits GEMM: [4096 x 10403], K=896 ----------------------
// A row r=(b*T+t) gathered from [attn(512) | emb(128) | h(256)], B = W_out (NT)
__global__ void logits_kernel(const float* __restrict__ Wout, const float* __restrict__ bout,
                              float* __restrict__ out) {
    int n0 = blockIdx.x * 64;   // v
    int m0 = blockIdx.y * 64;   // r
    __shared__ __align__(16) float sA[16][68];  // [k][m]
    __shared__ __align__(16) float sB[16][68];  // [k][n]
    int tid = threadIdx.x;
    int tx = tid & 15, ty = tid >> 4;
    float acc[4][4] = {};
    for (int k0 = 0; k0 < Kcat; k0 += 16) {
        const float* base; int rs, koff;
        if (k0 < Cc)            { base = g_attn; rs = Cc; koff = k0; }
        else if (k0 < Cc + Ee)  { base = g_xemb; rs = Ee; koff = k0 - Cc; }
        else                    { base = g_hall; rs = Uu; koff = k0 - Cc - Ee; }
        #pragma unroll
        for (int i = 0; i < 4; i++) {
            int id = tid + i*256;
            int mm = id >> 4, k = id & 15;
            sA[k][mm] = base[(size_t)(m0+mm)*rs + koff + k];
        }
        #pragma unroll
        for (int i = 0; i < 4; i++) {
            int id = tid + i*256;
            int nn = id >> 4, k = id & 15;
            int v = n0 + nn;
            sB[k][nn] = (v < Vv) ? Wout[(size_t)v*Kcat + k0 + k] : 0.f;
        }
        __syncthreads();
        #pragma unroll
        for (int kk = 0; kk < 16; kk++) {
            float4 a4 = *(const float4*)&sA[kk][ty*4];
            float4 b4 = *(const float4*)&sB[kk][tx*4];
            acc[0][0] += a4.x*b4.x; acc[0][1] += a4.x*b4.y; acc[0][2] += a4.x*b4.z; acc[0][3] += a4.x*b4.w;
            acc[1][0] += a4.y*b4.x; acc[1][1] += a4.y*b4.y; acc[1][2] += a4.y*b4.z; acc[1][3] += a4.y*b4.w;
            acc[2][0] += a4.z*b4.x; acc[2][1] += a4.z*b4.y; acc[2][2] += a4.z*b4.z; acc[2][3] += a4.z*b4.w;
            acc[3][0] += a4.w*b4.x; acc[3][1] += a4.w*b4.y; acc[3][2] += a4.w*b4.z; acc[3][3] += a4.w*b4.w;
        }
        __syncthreads();
    }
    #pragma unroll
    for (int i = 0; i < 4; i++) {
        int r = m0 + ty*4 + i;
        #pragma unroll
        for (int j = 0; j < 4; j++) {
            int v = n0 + tx*4 + j;
            if (v < Vv) out[(size_t)r*Vv + v] = acc[i][j] + bout[v];
        }
    }
}

// ---------------- launch ---------------------------------------------------------
extern "C" void kernel_launch(void* const* d_in, const int* in_sizes, int n_in,
                              void* d_out, int out_size) {
    const float* img  = (const float*)d_in[0];
    const int*   ix   = (const int*)d_in[1];
    const float* Wh0  = (const float*)d_in[2];
    const float* bh0  = (const float*)d_in[3];
    const float* Wc0  = (const float*)d_in[4];
    const float* bc0  = (const float*)d_in[5];
    const float* Wkey = (const float*)d_in[6];
    const float* bkey = (const float*)d_in[7];
    const float* emb  = (const float*)d_in[8];
    const float* Wih  = (const float*)d_in[9];
    const float* bih  = (const float*)d_in[10];
    const float* Whh  = (const float*)d_in[11];
    const float* bhh  = (const float*)d_in[12];
    const float* Wout = (const float*)d_in[13];
    const float* bout = (const float*)d_in[14];

    float* out  = (float*)d_out;                       // logits [B,T,V]
    float* maps = out + (size_t)Bb * Tt * Vv;          // maps   [B,T,P]

    mean_kernel<<<(Bb*Cc)/8, 256>>>(img);
    hc0_kernel<<<Bb, 256>>>(Wh0, bh0, Wc0, bc0);
    emb_kernel<<<(Bb*Tt*Ee)/256, 256>>>(ix, emb);
    keys_kernel<<<dim3((Pp + 63)/64, Uu/64, Bb), 256>>>(Wkey, bkey, img);

    for (int t = 0; t < Tt; t++) {
        attn_kernel<<<Bb, 256>>>(t, img, maps);
        gates_kernel<<<dim3(Gg/64, Bb/16), 256>>>(t, Wih, bih, Whh, bhh);
        lstm_kernel<<<Bb, 256>>>(t);
    }

    logits_kernel<<<dim3((Vv + 63)/64, (Bb*Tt)/64), 256>>>(Wout, bout, out);
}